// round 10
// baseline (speedup 1.0000x reference)
#include <cuda_runtime.h>

// Problem constants (fixed shapes from reference):
//   B=4, S=64, F=64, V=16384, E=512, rows = B*S*F = 16384
#define V_DIM 16384
#define E_DIM 512
#define NROWS 16384
#define TPB   64                 // 2 warps per CTA
#define BURST 8                  // float4 loads per lane per burst
#define BELEM (BURST * 32 * 4)   // 1024 elements per burst
#define NBURST (V_DIM / BELEM)   // 16 bursts per row
#define GRID  2960               // ~148 SMs x 20 resident CTAs; queue handles the rest

// Persistent-warp burst scan with an atomic row queue.
//   R9 calibration: the burst engine delivers 0.73 B/cy/warp, but static
//   row assignment left only ~31 of ~42 provisioned warps active (2.6-wave
//   quantization + early-exit variance) -> 76% DRAM. Here every warp pulls
//   rows from a global counter until the queue drains, pinning active warps
//   at the resident count. Expected BW: 6028 x 40/31 -> clips at chip cap.
//   Burst: 8 independent float4 per lane (4KB/warp in flight), one 0/1-sum
//   + ballot check per burst, exit at burst granularity (53.1% of x read).
// Phase B: out[row,:] = W[:,idx] + pos_emb[s,:] + fmap_emb[f,:]; W gathered
// column-wise (sector amplification absorbed by L2; x is __ldcs evict-first,
// out is __stcs, so W stays L2-resident).

__device__ int g_row_counter;

__global__ void reset_counter_kernel() {
    g_row_counter = 0;
}

__global__ void __launch_bounds__(TPB) combined_embedding_kernel(
    const float* __restrict__ x,
    const float* __restrict__ W,
    const float* __restrict__ pos_emb,
    const float* __restrict__ fmap_emb,
    float* __restrict__ out)
{
    const int lane = threadIdx.x & 31;

    while (true) {
        // ---- Pull next row from the queue (one atomic per row per warp) ----
        int row;
        if (lane == 0) row = atomicAdd(&g_row_counter, 1);
        row = __shfl_sync(0xffffffffu, row, 0);
        if (row >= NROWS) return;

        const float4* xr = reinterpret_cast<const float4*>(x + (size_t)row * V_DIM);

        int idx = -1;

        #pragma unroll 1
        for (int b = 0; b < NBURST; b++) {
            // 8 independent loads back-to-back: 4KB in flight for this warp.
            float4 v0 = __ldcs(&xr[b * 256 + 0 * 32 + lane]);
            float4 v1 = __ldcs(&xr[b * 256 + 1 * 32 + lane]);
            float4 v2 = __ldcs(&xr[b * 256 + 2 * 32 + lane]);
            float4 v3 = __ldcs(&xr[b * 256 + 3 * 32 + lane]);
            float4 v4 = __ldcs(&xr[b * 256 + 4 * 32 + lane]);
            float4 v5 = __ldcs(&xr[b * 256 + 5 * 32 + lane]);
            float4 v6 = __ldcs(&xr[b * 256 + 6 * 32 + lane]);
            float4 v7 = __ldcs(&xr[b * 256 + 7 * 32 + lane]);

            // 0/1 data: sum != 0 <=> this lane saw the one-hot element.
            float s = v0.x + v0.y + v0.z + v0.w
                    + v1.x + v1.y + v1.z + v1.w
                    + v2.x + v2.y + v2.z + v2.w
                    + v3.x + v3.y + v3.z + v3.w
                    + v4.x + v4.y + v4.z + v4.w
                    + v5.x + v5.y + v5.z + v5.w
                    + v6.x + v6.y + v6.z + v6.w
                    + v7.x + v7.y + v7.z + v7.w;

            const unsigned m = __ballot_sync(0xffffffffu, s != 0.0f);
            if (m) {
                // Rare path (once per row): locate the element within the burst.
                int f = -1;
                const float4 vv[8] = {v0, v1, v2, v3, v4, v5, v6, v7};
                #pragma unroll
                for (int j = 0; j < 8; j++) {
                    const int base = (b * 256 + j * 32 + lane) * 4;
                    if (vv[j].x != 0.0f) f = base + 0;
                    if (vv[j].y != 0.0f) f = base + 1;
                    if (vv[j].z != 0.0f) f = base + 2;
                    if (vv[j].w != 0.0f) f = base + 3;
                }
                const int src = __ffs(m) - 1;
                idx = __shfl_sync(0xffffffffu, f, src);
                break;
            }
        }
        if (idx < 0) idx = 0;

        // ---- Phase B: gather + add, warp-wide ----
        const int sr = (row >> 6) & 63;              // row = ((b*64)+s)*64 + f
        const int fm = row & 63;

        const float4* pe = reinterpret_cast<const float4*>(pos_emb  + (size_t)sr * E_DIM);
        const float4* fe = reinterpret_cast<const float4*>(fmap_emb + (size_t)fm * E_DIM);
        float4* o = reinterpret_cast<float4*>(out + (size_t)row * E_DIM);

        // E=512 -> 128 float4; 32 lanes x 4. W gather: column idx, stride V.
        #pragma unroll
        for (int j = 0; j < 4; j++) {
            const int q = j * 32 + lane;             // float4 index within row
            const int e = q * 4;
            float4 p = __ldg(&pe[q]);
            float4 g = __ldg(&fe[q]);
            float4 r;
            r.x = __ldg(&W[(size_t)(e + 0) * V_DIM + idx]) + p.x + g.x;
            r.y = __ldg(&W[(size_t)(e + 1) * V_DIM + idx]) + p.y + g.y;
            r.z = __ldg(&W[(size_t)(e + 2) * V_DIM + idx]) + p.z + g.z;
            r.w = __ldg(&W[(size_t)(e + 3) * V_DIM + idx]) + p.w + g.w;
            __stcs(&o[q], r);                        // streaming: protect W in L2
        }
    }
}

extern "C" void kernel_launch(void* const* d_in, const int* in_sizes, int n_in,
                              void* d_out, int out_size) {
    const float* x        = (const float*)d_in[0];  // [4,64,64,16384]
    const float* W        = (const float*)d_in[1];  // [512,16384]
    const float* pos_emb  = (const float*)d_in[2];  // [256,512]
    const float* fmap_emb = (const float*)d_in[3];  // [256,512]
    float* out = (float*)d_out;                     // [4,64,64,512]

    (void)in_sizes; (void)n_in; (void)out_size;

    reset_counter_kernel<<<1, 1>>>();
    combined_embedding_kernel<<<GRID, TPB>>>(x, W, pos_emb, fmap_emb, out);
}

// round 11
// speedup vs baseline: 1.0130x; 1.0130x over previous
#include <cuda_runtime.h>

// Problem constants (fixed shapes from reference):
//   B=4, S=64, F=64, V=16384, E=512, rows = B*S*F = 16384
#define V_DIM 16384
#define E_DIM 512
#define NROWS 16384
#define TPB   64                 // 2 warps per CTA
#define WPB   (TPB / 32)
#define BURST 16                 // float4 loads per lane per burst (8KB/warp)
#define BELEM (BURST * 32 * 4)   // 2048 elements per burst
#define NBURST (V_DIM / BELEM)   // 8 bursts per row

// Warp-per-row scan with an 8KB-per-warp burst window (R1's proven issue
// depth) and early exit at burst granularity.
//   R10 analysis: every early-exit check is a dependency wall (next burst
//   can't issue until the ballot's branch resolves), so per-warp rate =
//   burst_bytes / L_loaded. Doubling the burst from 4KB (R9, 76% DRAM) to
//   8KB doubles the rate at the cost of +3pp over-read (56.25% of x).
//   Index reconstruction by FMA instead of a compare tree: x is exactly
//   {0,1} with one 1 per row, so T = sum(v) and Ws = sum(c_jk * v) with
//   compile-time c_jk = j*128+k (FFMA-imm) give, in the hit lane,
//   element = b*2048 + 4*lane + Ws. Each float4 is consumed immediately
//   after arrival (short live ranges -> regs stay moderate), and the hit
//   path needs no stored array or re-scan.
// Phase B: out[row,:] = W[:,idx] + pos_emb[s,:] + fmap_emb[f,:]; W gathered
// column-wise (sector amplification absorbed by L2; x is __ldcs evict-first,
// out is __stcs, so W stays L2-resident).
__global__ void __launch_bounds__(TPB) combined_embedding_kernel(
    const float* __restrict__ x,
    const float* __restrict__ W,
    const float* __restrict__ pos_emb,
    const float* __restrict__ fmap_emb,
    float* __restrict__ out)
{
    const int warp = threadIdx.x >> 5;
    const int lane = threadIdx.x & 31;
    const int row  = blockIdx.x * WPB + warp;

    const float4* xr = reinterpret_cast<const float4*>(x + (size_t)row * V_DIM);

    int idx = -1;

    #pragma unroll 1
    for (int b = 0; b < NBURST; b++) {
        // 16 independent float4 loads: 8KB in flight for this warp.
        float4 v[BURST];
        #pragma unroll
        for (int j = 0; j < BURST; j++)
            v[j] = __ldcs(&xr[b * (BURST * 32) + j * 32 + lane]);

        // Consume on arrival: T = sum(v), Ws = sum(c_jk * v), c_jk immediate.
        float T = 0.0f, Ws = 0.0f;
        #pragma unroll
        for (int j = 0; j < BURST; j++) {
            const float c0 = (float)(j * 128 + 0);
            const float c1 = (float)(j * 128 + 1);
            const float c2 = (float)(j * 128 + 2);
            const float c3 = (float)(j * 128 + 3);
            T += v[j].x; Ws = fmaf(v[j].x, c0, Ws);
            T += v[j].y; Ws = fmaf(v[j].y, c1, Ws);
            T += v[j].z; Ws = fmaf(v[j].z, c2, Ws);
            T += v[j].w; Ws = fmaf(v[j].w, c3, Ws);
        }

        const unsigned m = __ballot_sync(0xffffffffu, T != 0.0f);
        if (m) {
            // Hit lane: exactly one element == 1.0, so T == 1 and Ws == c_jk.
            const int f = b * BELEM + lane * 4 + (int)Ws;
            const int src = __ffs(m) - 1;
            idx = __shfl_sync(0xffffffffu, f, src);
            break;
        }
    }
    if (idx < 0) idx = 0;

    // ---- Phase B: gather + add, warp-wide ----
    {
        const int s  = (row >> 6) & 63;              // row = ((b*64)+s)*64 + f
        const int fm = row & 63;

        const float4* pe = reinterpret_cast<const float4*>(pos_emb  + (size_t)s  * E_DIM);
        const float4* fe = reinterpret_cast<const float4*>(fmap_emb + (size_t)fm * E_DIM);
        float4* o = reinterpret_cast<float4*>(out + (size_t)row * E_DIM);

        // E=512 -> 128 float4; 32 lanes x 4. W gather: column idx, stride V.
        #pragma unroll
        for (int j = 0; j < 4; j++) {
            const int q = j * 32 + lane;             // float4 index within row
            const int e = q * 4;
            float4 p = __ldg(&pe[q]);
            float4 g = __ldg(&fe[q]);
            float4 r;
            r.x = __ldg(&W[(size_t)(e + 0) * V_DIM + idx]) + p.x + g.x;
            r.y = __ldg(&W[(size_t)(e + 1) * V_DIM + idx]) + p.y + g.y;
            r.z = __ldg(&W[(size_t)(e + 2) * V_DIM + idx]) + p.z + g.z;
            r.w = __ldg(&W[(size_t)(e + 3) * V_DIM + idx]) + p.w + g.w;
            __stcs(&o[q], r);                        // streaming: protect W in L2
        }
    }
}

extern "C" void kernel_launch(void* const* d_in, const int* in_sizes, int n_in,
                              void* d_out, int out_size) {
    const float* x        = (const float*)d_in[0];  // [4,64,64,16384]
    const float* W        = (const float*)d_in[1];  // [512,16384]
    const float* pos_emb  = (const float*)d_in[2];  // [256,512]
    const float* fmap_emb = (const float*)d_in[3];  // [256,512]
    float* out = (float*)d_out;                     // [4,64,64,512]

    (void)in_sizes; (void)n_in; (void)out_size;

    combined_embedding_kernel<<<NROWS / WPB, TPB>>>(x, W, pos_emb, fmap_emb, out);
}